// round 9
// baseline (speedup 1.0000x reference)
#include <cuda_runtime.h>
#include <math.h>

// Problem constants
#define HW    4096
#define WIDTH 64
#define BATCH 4

// Scratch (device globals — no allocation allowed in kernel_launch)
static __device__ float g_qkv[(size_t)BATCH * 768 * HW];   // (B,768,HW)
static __device__ float g_att[(size_t)BATCH * 256 * HW];   // (B,256,HW), tf32-rounded at store
static __device__ float g_xr[(size_t)BATCH * 256 * HW];    // tf32-rounded x
static __device__ float g_wqkv[768 * 256];                 // tf32-rounded qkv_w
static __device__ float g_wproj[256 * 256];                // tf32-rounded proj_w

// ---------------------------------------------------------------------------
__device__ __forceinline__ float tf32r(float x) {
    unsigned u;
    asm("cvt.rna.tf32.f32 %0, %1;" : "=r"(u) : "f"(x));
    return __uint_as_float(u);
}

__global__ void round_tf32_copy(const float* __restrict__ in,
                                float* __restrict__ out, int n4)
{
    int i = blockIdx.x * blockDim.x + threadIdx.x;
    if (i < n4) {
        float4 v = ((const float4*)in)[i];
        ((float4*)out)[i] = make_float4(tf32r(v.x), tf32r(v.y), tf32r(v.z), tf32r(v.w));
    }
}

__device__ __forceinline__ void mma_tf32(float c[4], const unsigned a[4], const unsigned b[2]) {
    asm volatile(
        "mma.sync.aligned.m16n8k8.row.col.f32.tf32.tf32.f32 "
        "{%0,%1,%2,%3}, {%4,%5,%6,%7}, {%8,%9}, {%0,%1,%2,%3};\n"
        : "+f"(c[0]), "+f"(c[1]), "+f"(c[2]), "+f"(c[3])
        : "r"(a[0]), "r"(a[1]), "r"(a[2]), "r"(a[3]), "r"(b[0]), "r"(b[1]));
}

__device__ __forceinline__ void ldsm_x4(unsigned r[4], const float* p) {
    unsigned addr = (unsigned)__cvta_generic_to_shared(p);
    asm volatile(
        "ldmatrix.sync.aligned.m8n8.x4.shared.b16 {%0,%1,%2,%3}, [%4];"
        : "=r"(r[0]), "=r"(r[1]), "=r"(r[2]), "=r"(r[3]) : "r"(addr));
}

__device__ __forceinline__ void cp_async16(void* smem, const void* gmem) {
    unsigned s = (unsigned)__cvta_generic_to_shared(smem);
    asm volatile("cp.async.cg.shared.global [%0], [%1], 16;" :: "r"(s), "l"(gmem));
}
#define CP_COMMIT() asm volatile("cp.async.commit_group;")
#define CP_WAIT0()  asm volatile("cp.async.wait_group 0;" ::: "memory")

// ---------------------------------------------------------------------------
// TF32 tensor-core GEMM with bias (R8 winner, unchanged).
// ---------------------------------------------------------------------------
#define BK   32
#define PADK 36
#define PADN 136
#define AS_STAGE (128 * PADK)
#define BS_STAGE (BK * PADN)
#define SMEM_FLOATS (2 * AS_STAGE + 2 * BS_STAGE)
#define SMEM_BYTES  (SMEM_FLOATS * 4)

__global__ void __launch_bounds__(256, 2) gemm_tf32_bias(
    const float* __restrict__ W, const float* __restrict__ X,
    const float* __restrict__ bias, float* __restrict__ C,
    int M, int N, int K)
{
    extern __shared__ float smem[];
    float* const Abase = smem;
    float* const Bbase = smem + 2 * AS_STAGE;

    const int b  = blockIdx.z;
    const float* Xb = X + (size_t)b * K * N;
    float*       Cb = C + (size_t)b * M * N;
    const int m0 = blockIdx.y * 128;
    const int n0 = blockIdx.x * 128;
    const int tid  = threadIdx.x;
    const int lane = tid & 31;
    const int warp = tid >> 5;
    const int wm = (warp >> 2) * 64;
    const int wn = (warp & 3) * 32;
    const int g  = lane >> 2;
    const int t  = lane & 3;

    const int row_a = lane & 15;
    const int col_a = (lane >> 4) * 4;

    const int ar = tid & 127;
    const int akb = (tid >> 7) * 16;
    const int br = tid >> 5;
    const int bc = (tid & 31) * 4;

    const float* gA = &W[(size_t)(m0 + ar) * K + akb];
    const float* gB = &Xb[(size_t)br * N + n0 + bc];

    float acc[4][4][4];
#pragma unroll
    for (int i = 0; i < 4; ++i)
#pragma unroll
        for (int j = 0; j < 4; ++j)
#pragma unroll
            for (int r = 0; r < 4; ++r) acc[i][j][r] = 0.f;

    {
        float* sA = Abase + ar * PADK + akb;
        float* sB = Bbase + br * PADN + bc;
#pragma unroll
        for (int i = 0; i < 4; ++i)
            cp_async16(sA + i * 4, gA + i * 4);
#pragma unroll
        for (int j = 0; j < 4; ++j)
            cp_async16(sB + j * 8 * PADN, gB + (size_t)j * 8 * N);
    }
    CP_COMMIT();
    CP_WAIT0();
    __syncthreads();

    int cur = 0;
    for (int k0 = 0; k0 < K; k0 += BK) {
        const bool has_next = (k0 + BK < K);
        if (has_next) {
            const int nxt = cur ^ 1;
            float* sA = Abase + nxt * AS_STAGE + ar * PADK + akb;
            float* sB = Bbase + nxt * BS_STAGE + br * PADN + bc;
#pragma unroll
            for (int i = 0; i < 4; ++i)
                cp_async16(sA + i * 4, gA + k0 + BK + i * 4);
#pragma unroll
            for (int j = 0; j < 4; ++j)
                cp_async16(sB + j * 8 * PADN, gB + (size_t)(k0 + BK + j * 8) * N);
            CP_COMMIT();
        }

        const float* As = Abase + cur * AS_STAGE;
        const float* Bs = Bbase + cur * BS_STAGE;
#pragma unroll
        for (int kk = 0; kk < BK; kk += 8) {
            unsigned af[4][4], bf[4][2];
#pragma unroll
            for (int mt = 0; mt < 4; ++mt)
                ldsm_x4(af[mt], As + (wm + mt * 16 + row_a) * PADK + kk + col_a);
#pragma unroll
            for (int nt = 0; nt < 4; ++nt) {
                const int nb = wn + nt * 8;
                bf[nt][0] = __float_as_uint(Bs[(kk + t    ) * PADN + nb + g]);
                bf[nt][1] = __float_as_uint(Bs[(kk + t + 4) * PADN + nb + g]);
            }
#pragma unroll
            for (int mt = 0; mt < 4; ++mt)
#pragma unroll
                for (int nt = 0; nt < 4; ++nt)
                    mma_tf32(acc[mt][nt], af[mt], bf[nt]);
        }

        if (has_next) {
            CP_WAIT0();
            __syncthreads();
            cur ^= 1;
        }
    }

#pragma unroll
    for (int mt = 0; mt < 4; ++mt) {
#pragma unroll
        for (int rh = 0; rh < 2; ++rh) {
            const int m = m0 + wm + mt * 16 + g + rh * 8;
            const float bv = bias[m];
#pragma unroll
            for (int nt = 0; nt < 4; ++nt) {
                float2 o;
                o.x = acc[mt][nt][rh * 2 + 0] + bv;
                o.y = acc[mt][nt][rh * 2 + 1] + bv;
                *(float2*)&Cb[(size_t)m * N + n0 + wn + nt * 8 + t * 2] = o;
            }
        }
    }
}

// ---------------------------------------------------------------------------
// Fused multi-range neighborhood attention, pixel-pair + d-split version.
// Thread handles pixels (x, y1) and (x, y1+DIL) for 16 channels (d-half);
// lane^16 holds the other 16 channels; dots completed via shfl_xor(16).
// Each loaded k/v row serves both pixels (rows overlap for the y-pair),
// cutting LDG instruction count per pixel by ~(KS+1)/(2KS).
// OOB neighbors: k=v=0 -> exp(0)*erpb = erpb with zero v — matches jnp.pad.
// ---------------------------------------------------------------------------
template<int KS, int DIL>
__device__ __forceinline__ void attend_pair(
    const float* __restrict__ qb, const float* __restrict__ kb,
    const float* __restrict__ vb, const float* __restrict__ s_erpb,
    float* __restrict__ ob, int x, int ty, int db)
{
    constexpr int c = KS / 2;
    constexpr int NY1 = (DIL == 3) ? 33 : 32;
    if (ty >= NY1) return;

    const int y1 = (ty / DIL) * (2 * DIL) + (ty % DIL);
    const int y2 = y1 + DIL;
    const bool has2 = (y2 < WIDTH);

    const int idx1 = y1 * WIDTH + x;
    const int idx2 = y2 * WIDTH + x;   // memory-safe even if y2 >= 64 (stays in g_qkv)

    float q1[16], q2[16];
#pragma unroll
    for (int d = 0; d < 16; ++d) {
        q1[d] = qb[(size_t)(db + d) * HW + idx1] * 0.17677669529663687f;
        q2[d] = qb[(size_t)(db + d) * HW + idx2] * 0.17677669529663687f;
    }

    float s1 = 0.f, s2 = 0.f;
    float acc1[16], acc2[16];
#pragma unroll
    for (int d = 0; d < 16; ++d) { acc1[d] = 0.f; acc2[d] = 0.f; }

#pragma unroll 1
    for (int r = 0; r <= KS; ++r) {
        const int ny = y1 + (r - c) * DIL;
        const bool vy = ((unsigned)ny < (unsigned)WIDTH);
        const int rowo = ny * WIDTH;
#pragma unroll 1
        for (int j = 0; j < KS; ++j) {
            const int nx = x + (j - c) * DIL;
            const bool val = vy && ((unsigned)nx < (unsigned)WIDTH);
            const int nidx = rowo + nx;

            float kk[16], vv[16];
#pragma unroll
            for (int d = 0; d < 16; ++d) {
                kk[d] = val ? kb[(size_t)(db + d) * HW + nidx] : 0.f;
                vv[d] = val ? vb[(size_t)(db + d) * HW + nidx] : 0.f;
            }

            if (r < KS) {   // neighbor (r, j) of pixel 1
                float c0 = q1[0] * kk[0], c1 = q1[1] * kk[1];
                float c2 = q1[2] * kk[2], c3 = q1[3] * kk[3];
#pragma unroll
                for (int d = 4; d < 16; d += 4) {
                    c0 += q1[d + 0] * kk[d + 0];
                    c1 += q1[d + 1] * kk[d + 1];
                    c2 += q1[d + 2] * kk[d + 2];
                    c3 += q1[d + 3] * kk[d + 3];
                }
                float pd = (c0 + c1) + (c2 + c3);
                float dot = pd + __shfl_xor_sync(0xffffffffu, pd, 16);
                float p = __expf(dot) * s_erpb[r * KS + j];
                s1 += p;
#pragma unroll
                for (int d = 0; d < 16; ++d)
                    acc1[d] += p * vv[d];
            }
            if (r >= 1) {   // neighbor (r-1, j) of pixel 2
                float c0 = q2[0] * kk[0], c1 = q2[1] * kk[1];
                float c2 = q2[2] * kk[2], c3 = q2[3] * kk[3];
#pragma unroll
                for (int d = 4; d < 16; d += 4) {
                    c0 += q2[d + 0] * kk[d + 0];
                    c1 += q2[d + 1] * kk[d + 1];
                    c2 += q2[d + 2] * kk[d + 2];
                    c3 += q2[d + 3] * kk[d + 3];
                }
                float pd = (c0 + c1) + (c2 + c3);
                float dot = pd + __shfl_xor_sync(0xffffffffu, pd, 16);
                float p = __expf(dot) * s_erpb[(r - 1) * KS + j];
                s2 += p;
#pragma unroll
                for (int d = 0; d < 16; ++d)
                    acc2[d] += p * vv[d];
            }
        }
    }

    const float inv1 = 1.f / s1;
#pragma unroll
    for (int d = 0; d < 16; ++d)
        ob[(size_t)(db + d) * HW + idx1] = tf32r(acc1[d] * inv1);
    if (has2) {
        const float inv2 = 1.f / s2;
#pragma unroll
        for (int d = 0; d < 16; ++d)
            ob[(size_t)(db + d) * HW + idx2] = tf32r(acc2[d] * inv2);
    }
}

__global__ void __launch_bounds__(128) attn_fused(
    const float* __restrict__ qkv,
    const float* __restrict__ rpb0, const float* __restrict__ rpb1,
    const float* __restrict__ rpb2, float* __restrict__ att)
{
    __shared__ float s_erpb[81];

    const int bh = blockIdx.z;
    const int b  = bh >> 3;
    const int h  = bh & 7;
    const int tid = threadIdx.y * 32 + threadIdx.x;

    if (h < 4) {
        if (tid < 25) s_erpb[tid] = __expf(rpb0[h * 25 + tid]);
    } else if (h < 7) {
        if (tid < 49) s_erpb[tid] = __expf(rpb1[(h - 4) * 49 + tid]);
    } else {
        if (tid < 81) s_erpb[tid] = __expf(rpb2[tid]);
    }
    __syncthreads();

    const int lane = threadIdx.x;
    const int x  = blockIdx.x * 16 + (lane & 15);
    const int db = (lane >> 4) * 16;                 // d-half: 0 or 16
    const int ty = blockIdx.y * 4 + threadIdx.y;     // y1-pair index

    const float* qb = qkv + ((size_t)b * 768 + h * 32) * HW;
    const float* kb = qb + (size_t)256 * HW;
    const float* vb = qb + (size_t)512 * HW;
    float* ob = att + ((size_t)b * 256 + h * 32) * HW;

    if (h < 4)       attend_pair<5, 1>(qb, kb, vb, s_erpb, ob, x, ty, db);
    else if (h < 7)  attend_pair<7, 2>(qb, kb, vb, s_erpb, ob, x, ty, db);
    else             attend_pair<9, 3>(qb, kb, vb, s_erpb, ob, x, ty, db);
}

// ---------------------------------------------------------------------------
extern "C" void kernel_launch(void* const* d_in, const int* in_sizes, int n_in,
                              void* d_out, int out_size)
{
    const float* x      = (const float*)d_in[0];
    const float* qkv_w  = (const float*)d_in[1];
    const float* qkv_b  = (const float*)d_in[2];
    const float* proj_w = (const float*)d_in[3];
    const float* proj_b = (const float*)d_in[4];
    const float* rpb0   = (const float*)d_in[5];
    const float* rpb1   = (const float*)d_in[6];
    const float* rpb2   = (const float*)d_in[7];
    float* out = (float*)d_out;

    float *qkv_ptr, *att_ptr, *xr_ptr, *wqkv_ptr, *wproj_ptr;
    cudaGetSymbolAddress((void**)&qkv_ptr,  g_qkv);
    cudaGetSymbolAddress((void**)&att_ptr,  g_att);
    cudaGetSymbolAddress((void**)&xr_ptr,   g_xr);
    cudaGetSymbolAddress((void**)&wqkv_ptr, g_wqkv);
    cudaGetSymbolAddress((void**)&wproj_ptr,g_wproj);

    static bool attr_set = false;
    if (!attr_set) {
        cudaFuncSetAttribute(gemm_tf32_bias,
                             cudaFuncAttributeMaxDynamicSharedMemorySize, SMEM_BYTES);
        attr_set = true;
    }

    // 0) Pre-round GEMM inputs to tf32
    round_tf32_copy<<<(BATCH * 256 * HW / 4 + 255) / 256, 256>>>(x, xr_ptr, BATCH * 256 * HW / 4);
    round_tf32_copy<<<(768 * 256 / 4 + 255) / 256, 256>>>(qkv_w, wqkv_ptr, 768 * 256 / 4);
    round_tf32_copy<<<(256 * 256 / 4 + 255) / 256, 256>>>(proj_w, wproj_ptr, 256 * 256 / 4);

    // 1) QKV projection — TF32 tensor cores, BK=32
    gemm_tf32_bias<<<dim3(32, 6, BATCH), 256, SMEM_BYTES>>>(wqkv_ptr, xr_ptr, qkv_b, qkv_ptr, 768, HW, 256);

    // 2) Fused multi-range neighborhood attention (pixel-pair, d-split)
    attn_fused<<<dim3(4, 9, BATCH * 8), dim3(32, 4)>>>(qkv_ptr, rpb0, rpb1, rpb2, att_ptr);

    // 3) Output projection — TF32 tensor cores, BK=32
    gemm_tf32_bias<<<dim3(32, 2, BATCH), 256, SMEM_BYTES>>>(wproj_ptr, att_ptr, proj_b, out, 256, HW, 256);
}